// round 9
// baseline (speedup 1.0000x reference)
#include <cuda_runtime.h>
#include <cstdint>

// Complex attention, fp16 m16n8k16 mma.sync.
// 128-thread CTAs (4 warps, QT=64), 2 CTAs/SM for cross-CTA latency hiding.
// ldmatrix.x4 fragment loads, Q fragments register-resident, dbuf K/V, 1 bar/tile.

#define S_LEN   2048
#define DH      64
#define QT      64
#define NT      64
#define NTILES  (S_LEN / NT)
#define THREADS 128
#define NITEMS  1024            // 32 q-tiles x 32 heads
#define GRID    304
#define ROWB    176             // bytes per smem row (88 halves)
#define PL_STR  (NT * ROWB)     // 11264: plane stride inside a buffer group

#define KP(buf, pl) (((buf) * 2 + (pl)) * PL_STR)            // K: [0, 45056)
#define V_B     (4 * PL_STR)                                 // 45056
#define VP(buf, pl) (V_B + ((buf) * 2 + (pl)) * PL_STR)      // V: [45056, 90112)
#define SMEM_BYTES (8 * PL_STR)                              // 90112

__device__ unsigned int g_ticket;
__global__ void reset_ticket_kernel() { g_ticket = 0u; }

__device__ __forceinline__ uint32_t cvta_s(const void* p) {
    uint32_t a;
    asm("{ .reg .u64 t; cvta.to.shared.u64 t, %1; cvt.u32.u64 %0, t; }" : "=r"(a) : "l"(p));
    return a;
}
__device__ __forceinline__ uint32_t pkh(float lo, float hi) {
    uint32_t d; asm("cvt.rn.f16x2.f32 %0, %1, %2;" : "=r"(d) : "f"(hi), "f"(lo)); return d;
}
__device__ __forceinline__ uint4 ldsm4(uint32_t a) {
    uint4 r;
    asm volatile("ldmatrix.sync.aligned.m8n8.x4.shared.b16 {%0,%1,%2,%3}, [%4];"
        : "=r"(r.x), "=r"(r.y), "=r"(r.z), "=r"(r.w) : "r"(a));
    return r;
}
__device__ __forceinline__ void mma16(float* d, const uint32_t* a, uint32_t b0, uint32_t b1) {
    asm volatile(
        "mma.sync.aligned.m16n8k16.row.col.f32.f16.f16.f32 "
        "{%0,%1,%2,%3}, {%4,%5,%6,%7}, {%8,%9}, {%0,%1,%2,%3};"
        : "+f"(d[0]), "+f"(d[1]), "+f"(d[2]), "+f"(d[3])
        : "r"(a[0]), "r"(a[1]), "r"(a[2]), "r"(a[3]), "r"(b0), "r"(b1));
}

__global__ __launch_bounds__(THREADS, 2)
void cv_attn_h3_kernel(
    const float* __restrict__ qr, const float* __restrict__ qi,
    const float* __restrict__ kr, const float* __restrict__ ki,
    const float* __restrict__ vr, const float* __restrict__ vi,
    float* __restrict__ out, long long plane)
{
    extern __shared__ char sm[];
    __shared__ int s_item;
    const uint32_t smb = cvta_s(sm);

    const int tid  = threadIdx.x;
    const int w    = tid >> 5;
    const int lane = tid & 31;
    const int g4   = lane >> 2;
    const int j4   = lane & 3;
    const int r0   = w * 16 + g4;           // rows 0..63 (+8 for upper half)

    // loader maps
    const int kkey = tid >> 1, kdb = (tid & 1) * 32;    // K: 32 d of one key
    const int vd   = (tid & 31) * 2, vseg = (tid >> 5) * 16;  // V: 2 d-rows x 16 keys
    // per-lane ldmatrix base (row-in-group, k-high +16B, plane +PL_STR)
    const uint32_t laneLM = (uint32_t)((lane & 7) * ROWB)
                          + ((lane & 8) ? 16u : 0u)
                          + ((lane & 16) ? (uint32_t)PL_STR : 0u);

    for (;;) {
        if (tid == 0) s_item = (int)atomicAdd(&g_ticket, 1u);
        __syncthreads();                    // also orders prev item's smem reuse
        const int item = s_item;
        if (item >= NITEMS) break;

        const int bh  = item >> 5;
        const int s0t = (item & 31) * QT;
        const long long bb = (long long)bh * S_LEN * DH;

        float4 kra[8], kia[8];
        float2 vvr[16], vvi[16];

        auto ldK = [&](int t) {
            const float* g0 = kr + bb + (long long)(t * NT + kkey) * DH + kdb;
            const float* g1 = ki + bb + (long long)(t * NT + kkey) * DH + kdb;
            #pragma unroll
            for (int j = 0; j < 8; ++j) kra[j] = *(const float4*)(g0 + j * 4);
            #pragma unroll
            for (int j = 0; j < 8; ++j) kia[j] = *(const float4*)(g1 + j * 4);
        };
        auto stK = [&](int buf) {
            char* d0 = sm + KP(buf, 0) + kkey * ROWB + kdb * 2;
            char* d1 = sm + KP(buf, 1) + kkey * ROWB + kdb * 2;
            #pragma unroll
            for (int h = 0; h < 2; ++h) {
                *(uint4*)(d0 + h * 16) = make_uint4(
                    pkh(kra[h*2].x, kra[h*2].y),     pkh(kra[h*2].z, kra[h*2].w),
                    pkh(kra[h*2+1].x, kra[h*2+1].y), pkh(kra[h*2+1].z, kra[h*2+1].w));
                *(uint4*)(d1 + h * 16) = make_uint4(
                    pkh(kia[h*2].x, kia[h*2].y),     pkh(kia[h*2].z, kia[h*2].w),
                    pkh(kia[h*2+1].x, kia[h*2+1].y), pkh(kia[h*2+1].z, kia[h*2+1].w));
            }
            #pragma unroll
            for (int h = 2; h < 4; ++h) {
                *(uint4*)(d0 + h * 16) = make_uint4(
                    pkh(kra[h*2].x, kra[h*2].y),     pkh(kra[h*2].z, kra[h*2].w),
                    pkh(kra[h*2+1].x, kra[h*2+1].y), pkh(kra[h*2+1].z, kra[h*2+1].w));
                *(uint4*)(d1 + h * 16) = make_uint4(
                    pkh(kia[h*2].x, kia[h*2].y),     pkh(kia[h*2].z, kia[h*2].w),
                    pkh(kia[h*2+1].x, kia[h*2+1].y), pkh(kia[h*2+1].z, kia[h*2+1].w));
            }
        };
        auto ldV = [&](int t) {
            const float* g0 = vr + bb + (long long)(t * NT + vseg) * DH + vd;
            const float* g1 = vi + bb + (long long)(t * NT + vseg) * DH + vd;
            #pragma unroll
            for (int j = 0; j < 16; ++j) vvr[j] = *(const float2*)(g0 + j * DH);
            #pragma unroll
            for (int j = 0; j < 16; ++j) vvi[j] = *(const float2*)(g1 + j * DH);
        };
        auto stV = [&](int buf) {
            char* d0 = sm + VP(buf, 0) + vd * ROWB + vseg * 2;
            *(uint4*)(d0)      = make_uint4(pkh(vvr[0].x, vvr[1].x),  pkh(vvr[2].x, vvr[3].x),
                                            pkh(vvr[4].x, vvr[5].x),  pkh(vvr[6].x, vvr[7].x));
            *(uint4*)(d0 + 16) = make_uint4(pkh(vvr[8].x, vvr[9].x),  pkh(vvr[10].x, vvr[11].x),
                                            pkh(vvr[12].x, vvr[13].x),pkh(vvr[14].x, vvr[15].x));
            char* d0b = d0 + ROWB;
            *(uint4*)(d0b)      = make_uint4(pkh(vvr[0].y, vvr[1].y),  pkh(vvr[2].y, vvr[3].y),
                                             pkh(vvr[4].y, vvr[5].y),  pkh(vvr[6].y, vvr[7].y));
            *(uint4*)(d0b + 16) = make_uint4(pkh(vvr[8].y, vvr[9].y),  pkh(vvr[10].y, vvr[11].y),
                                             pkh(vvr[12].y, vvr[13].y),pkh(vvr[14].y, vvr[15].y));
            char* d1 = sm + VP(buf, 1) + vd * ROWB + vseg * 2;
            *(uint4*)(d1)      = make_uint4(pkh(vvi[0].x, vvi[1].x),  pkh(vvi[2].x, vvi[3].x),
                                            pkh(vvi[4].x, vvi[5].x),  pkh(vvi[6].x, vvi[7].x));
            *(uint4*)(d1 + 16) = make_uint4(pkh(vvi[8].x, vvi[9].x),  pkh(vvi[10].x, vvi[11].x),
                                            pkh(vvi[12].x, vvi[13].x),pkh(vvi[14].x, vvi[15].x));
            char* d1b = d1 + ROWB;
            *(uint4*)(d1b)      = make_uint4(pkh(vvi[0].y, vvi[1].y),  pkh(vvi[2].y, vvi[3].y),
                                             pkh(vvi[4].y, vvi[5].y),  pkh(vvi[6].y, vvi[7].y));
            *(uint4*)(d1b + 16) = make_uint4(pkh(vvi[8].y, vvi[9].y),  pkh(vvi[10].y, vvi[11].y),
                                             pkh(vvi[12].y, vvi[13].y),pkh(vvi[14].y, vvi[15].y));
        };

        // ---- Q fragments -> registers (scaled by 1/8), held for whole item ----
        uint32_t qfr[4][4], qfi[4][4];
        {
            const float* q0 = qr + bb + (long long)(s0t + r0) * DH;
            const float* q8 = qr + bb + (long long)(s0t + r0 + 8) * DH;
            const float* p0 = qi + bb + (long long)(s0t + r0) * DH;
            const float* p8 = qi + bb + (long long)(s0t + r0 + 8) * DH;
            #pragma unroll
            for (int ks = 0; ks < 4; ++ks) {
                const int c = ks * 16 + 2 * j4;
                float2 a0 = *(const float2*)(q0 + c),     a1 = *(const float2*)(q8 + c);
                float2 a2 = *(const float2*)(q0 + c + 8), a3 = *(const float2*)(q8 + c + 8);
                qfr[ks][0] = pkh(a0.x * 0.125f, a0.y * 0.125f);
                qfr[ks][1] = pkh(a1.x * 0.125f, a1.y * 0.125f);
                qfr[ks][2] = pkh(a2.x * 0.125f, a2.y * 0.125f);
                qfr[ks][3] = pkh(a3.x * 0.125f, a3.y * 0.125f);
                float2 b0 = *(const float2*)(p0 + c),     b1 = *(const float2*)(p8 + c);
                float2 b2 = *(const float2*)(p0 + c + 8), b3 = *(const float2*)(p8 + c + 8);
                qfi[ks][0] = pkh(b0.x * 0.125f, b0.y * 0.125f);
                qfi[ks][1] = pkh(b1.x * 0.125f, b1.y * 0.125f);
                qfi[ks][2] = pkh(b2.x * 0.125f, b2.y * 0.125f);
                qfi[ks][3] = pkh(b3.x * 0.125f, b3.y * 0.125f);
            }
        }

        // ---- prologue: tile 0 into buffer 0 ----
        ldK(0); ldV(0);
        stK(0); stV(0);
        __syncthreads();

        float ore[8][4], oim[8][4];
        #pragma unroll
        for (int nb = 0; nb < 8; ++nb)
            #pragma unroll
            for (int c = 0; c < 4; ++c) { ore[nb][c] = 0.f; oim[nb][c] = 0.f; }
        float l0 = 0.f, l1 = 0.f;

        for (int t = 0; t < NTILES; ++t) {
            const int cur = t & 1, nxt = cur ^ 1;
            const bool pf = (t + 1 < NTILES);
            if (pf) ldK(t + 1);             // latency hidden under GEMM1

            // ---- GEMM1: S[16 x 64] complex ----
            float sre[8][4], sim[8][4];
            #pragma unroll
            for (int nb = 0; nb < 8; ++nb)
                #pragma unroll
                for (int c = 0; c < 4; ++c) { sre[nb][c] = 0.f; sim[nb][c] = 0.f; }

            const uint32_t kbase = smb + (uint32_t)KP(cur, 0) + laneLM;
            #pragma unroll
            for (int ks = 0; ks < 4; ++ks) {
                uint32_t nqb[4];
                #pragma unroll
                for (int k = 0; k < 4; ++k) nqb[k] = qfi[ks][k] ^ 0x80008000u;
                #pragma unroll
                for (int nb = 0; nb < 8; ++nb) {
                    uint4 f = ldsm4(kbase + nb * (8 * ROWB) + ks * 32);
                    mma16(sre[nb], qfr[ks], f.x, f.y);
                    mma16(sre[nb], nqb,     f.z, f.w);
                    mma16(sim[nb], qfr[ks], f.z, f.w);
                    mma16(sim[nb], qfi[ks], f.x, f.y);
                }
            }

            if (pf) { stK(nxt); ldV(t + 1); }   // V latency hidden under epilogue

            // ---- cv-softmax epilogue (register-local) ----
            #pragma unroll
            for (int nb = 0; nb < 8; ++nb) {
                #pragma unroll
                for (int c = 0; c < 4; ++c) {
                    float re = sre[nb][c], im = sim[nb][c];
                    float m2  = fmaxf(fmaf(re, re, im * im), 1e-24f);
                    float inv = rsqrtf(m2);
                    float mag = m2 * inv;
                    float e   = __expf(mag);
                    if (c < 2) l0 += e; else l1 += e;
                    float p = e * inv;
                    sre[nb][c] = re * p;
                    sim[nb][c] = im * p;
                }
            }

            if (pf) stV(nxt);

            // ---- GEMM2: O += P @ V ----
            const uint32_t vbase = smb + (uint32_t)VP(cur, 0) + laneLM;
            #pragma unroll
            for (int ks = 0; ks < 4; ++ks) {
                uint32_t pa[4], pb[4], npb[4];
                pa[0] = pkh(sre[2*ks][0],   sre[2*ks][1]);
                pa[1] = pkh(sre[2*ks][2],   sre[2*ks][3]);
                pa[2] = pkh(sre[2*ks+1][0], sre[2*ks+1][1]);
                pa[3] = pkh(sre[2*ks+1][2], sre[2*ks+1][3]);
                pb[0] = pkh(sim[2*ks][0],   sim[2*ks][1]);
                pb[1] = pkh(sim[2*ks][2],   sim[2*ks][3]);
                pb[2] = pkh(sim[2*ks+1][0], sim[2*ks+1][1]);
                pb[3] = pkh(sim[2*ks+1][2], sim[2*ks+1][3]);
                #pragma unroll
                for (int k = 0; k < 4; ++k) npb[k] = pb[k] ^ 0x80008000u;

                #pragma unroll
                for (int nb = 0; nb < 8; ++nb) {
                    uint4 f = ldsm4(vbase + nb * (8 * ROWB) + ks * 32);
                    mma16(ore[nb], pa,  f.x, f.y);
                    mma16(ore[nb], npb, f.z, f.w);
                    mma16(oim[nb], pa,  f.z, f.w);
                    mma16(oim[nb], pb,  f.x, f.y);
                }
            }
            __syncthreads();    // STS(t+1) visible; cur bufs free for t+2 writes
        }

        // ---- normalize + stage + coalesced store ----
        l0 += __shfl_xor_sync(~0u, l0, 1); l0 += __shfl_xor_sync(~0u, l0, 2);
        l1 += __shfl_xor_sync(~0u, l1, 1); l1 += __shfl_xor_sync(~0u, l1, 2);
        const float il0 = 1.0f / l0, il1 = 1.0f / l1;

        float* stg = (float*)sm;            // [64][132]: cols 0..63 re, 64..127 im
        #pragma unroll
        for (int nb = 0; nb < 8; ++nb) {
            const int d0 = nb * 8 + 2 * j4;
            stg[ r0      * 132 + d0    ]      = ore[nb][0] * il0;
            stg[ r0      * 132 + d0 + 1]      = ore[nb][1] * il0;
            stg[(r0 + 8) * 132 + d0    ]      = ore[nb][2] * il1;
            stg[(r0 + 8) * 132 + d0 + 1]      = ore[nb][3] * il1;
            stg[ r0      * 132 + 64 + d0]     = oim[nb][0] * il0;
            stg[ r0      * 132 + 64 + d0 + 1] = oim[nb][1] * il0;
            stg[(r0 + 8) * 132 + 64 + d0]     = oim[nb][2] * il1;
            stg[(r0 + 8) * 132 + 64 + d0 + 1] = oim[nb][3] * il1;
        }
        __syncthreads();

        for (int i = tid; i < QT * 32; i += THREADS) {
            const int row = i >> 5, c = i & 31;
            float4 v = *(const float4*)(stg + row * 132 + c * 4);
            if (c < 16)
                *(float4*)(out + bb + (long long)(s0t + row) * DH + c * 4) = v;
            else
                *(float4*)(out + plane + bb + (long long)(s0t + row) * DH + (c - 16) * 4) = v;
        }
        // next-iteration ticket __syncthreads orders stage reuse
    }
}

extern "C" void kernel_launch(void* const* d_in, const int* in_sizes, int n_in,
                              void* d_out, int out_size) {
    const float* qr = (const float*)d_in[0];
    const float* qi = (const float*)d_in[1];
    const float* kr = (const float*)d_in[2];
    const float* ki = (const float*)d_in[3];
    const float* vr = (const float*)d_in[4];
    const float* vi = (const float*)d_in[5];

    const long long plane = (long long)in_sizes[0];   // B*H*S*D

    static int configured = 0;
    if (!configured) {
        cudaFuncSetAttribute(cv_attn_h3_kernel,
                             cudaFuncAttributeMaxDynamicSharedMemorySize, SMEM_BYTES);
        configured = 1;
    }

    reset_ticket_kernel<<<1, 1>>>();
    cv_attn_h3_kernel<<<GRID, THREADS, SMEM_BYTES>>>(qr, qi, kr, ki, vr, vi,
                                                     (float*)d_out, plane);
}

// round 10
// speedup vs baseline: 2.4440x; 2.4440x over previous
#include <cuda_runtime.h>
#include <cuda_fp16.h>
#include <cstdint>

// Complex attention, fp16 m16n8k16 mma.sync.
// Prep kernels convert Q(x1/8)/K -> fp16 and V -> fp16 transposed [d][s] in
// __device__ scratch; main kernel: cp.async dbuf K/Vt + ldmatrix + reg-resident
// Q frags + register-local cv-softmax. Persistent CTAs, 1 barrier/tile.

#define S_LEN   2048
#define DH      64
#define BH      32
#define QT      128
#define NT      64
#define NTILES  (S_LEN / NT)
#define THREADS 256
#define NITEMS  512             // 16 q-tiles x 32 heads
#define GRID    152
#define ROWB    176             // smem row stride (88 halves): conflict-free ldsm
#define PL_STR  (NT * ROWB)     // 11264

#define KP(buf, pl) (((buf) * 2 + (pl)) * PL_STR)
#define V_B     (4 * PL_STR)
#define VP(buf, pl) (V_B + ((buf) * 2 + (pl)) * PL_STR)
#define SMEM_BYTES (8 * PL_STR) // 90112

#define ELEMS (BH * S_LEN * DH)

__device__ __align__(16) __half gQr[ELEMS];
__device__ __align__(16) __half gQi[ELEMS];
__device__ __align__(16) __half gKr[ELEMS];
__device__ __align__(16) __half gKi[ELEMS];
__device__ __align__(16) __half gVtr[ELEMS];   // [bh][d][s]
__device__ __align__(16) __half gVti[ELEMS];

__device__ unsigned int g_ticket;
__global__ void reset_ticket_kernel() { g_ticket = 0u; }

// ---- prep: elementwise fp32 -> fp16 (Q scaled by 1/8) ----
__global__ void conv_kernel(const float* __restrict__ q_r, const float* __restrict__ q_i,
                            const float* __restrict__ k_r, const float* __restrict__ k_i)
{
    const int ts = blockIdx.y;
    const float* src = (ts == 0) ? q_r : (ts == 1) ? q_i : (ts == 2) ? k_r : k_i;
    __half* dst = (ts == 0) ? gQr : (ts == 1) ? gQi : (ts == 2) ? gKr : gKi;
    const float sc = (ts < 2) ? 0.125f : 1.0f;
    const int n4 = ELEMS / 4;
    for (int i = blockIdx.x * blockDim.x + threadIdx.x; i < n4; i += gridDim.x * blockDim.x) {
        float4 v = ((const float4*)src)[i];
        __half2* d2 = (__half2*)(dst + (size_t)i * 4);
        d2[0] = __floats2half2_rn(v.x * sc, v.y * sc);
        d2[1] = __floats2half2_rn(v.z * sc, v.w * sc);
    }
}

// ---- prep: V [s][d] fp32 -> Vt [d][s] fp16 (tiled transpose) ----
__global__ void prep_vt_kernel(const float* __restrict__ v_r, const float* __restrict__ v_i)
{
    __shared__ float tr[32][33], ti[32][33];
    const int s0 = blockIdx.x * 32, d0 = blockIdx.y * 32, bh = blockIdx.z;
    const int tx = threadIdx.x, ty = threadIdx.y;
    const long long ib = (long long)bh * S_LEN * DH;
    #pragma unroll
    for (int k = 0; k < 4; ++k) {
        int r = ty + k * 8;
        tr[r][tx] = v_r[ib + (long long)(s0 + r) * DH + d0 + tx];
        ti[r][tx] = v_i[ib + (long long)(s0 + r) * DH + d0 + tx];
    }
    __syncthreads();
    const long long ob = (long long)bh * DH * S_LEN;
    #pragma unroll
    for (int k = 0; k < 4; ++k) {
        int r = ty + k * 8;
        gVtr[ob + (long long)(d0 + r) * S_LEN + s0 + tx] = __float2half_rn(tr[tx][r]);
        gVti[ob + (long long)(d0 + r) * S_LEN + s0 + tx] = __float2half_rn(ti[tx][r]);
    }
}

// ---- helpers ----
__device__ __forceinline__ uint32_t cvta_s(const void* p) {
    uint32_t a;
    asm("{ .reg .u64 t; cvta.to.shared.u64 t, %1; cvt.u32.u64 %0, t; }" : "=r"(a) : "l"(p));
    return a;
}
__device__ __forceinline__ void cpa16(uint32_t dst, const void* src) {
    asm volatile("cp.async.ca.shared.global [%0], [%1], 16;" :: "r"(dst), "l"(src));
}
#define CP_COMMIT() asm volatile("cp.async.commit_group;" ::: "memory")
#define CP_WAIT0()  asm volatile("cp.async.wait_group 0;" ::: "memory")

__device__ __forceinline__ uint32_t pkh(float lo, float hi) {
    uint32_t d; asm("cvt.rn.f16x2.f32 %0, %1, %2;" : "=r"(d) : "f"(hi), "f"(lo)); return d;
}
__device__ __forceinline__ uint4 ldsm4(uint32_t a) {
    uint4 r;
    asm volatile("ldmatrix.sync.aligned.m8n8.x4.shared.b16 {%0,%1,%2,%3}, [%4];"
        : "=r"(r.x), "=r"(r.y), "=r"(r.z), "=r"(r.w) : "r"(a));
    return r;
}
__device__ __forceinline__ void mma16(float* d, const uint32_t* a, uint32_t b0, uint32_t b1) {
    asm volatile(
        "mma.sync.aligned.m16n8k16.row.col.f32.f16.f16.f32 "
        "{%0,%1,%2,%3}, {%4,%5,%6,%7}, {%8,%9}, {%0,%1,%2,%3};"
        : "+f"(d[0]), "+f"(d[1]), "+f"(d[2]), "+f"(d[3])
        : "r"(a[0]), "r"(a[1]), "r"(a[2]), "r"(a[3]), "r"(b0), "r"(b1));
}

__global__ __launch_bounds__(THREADS, 1)
void cv_attn_h4_kernel(float* __restrict__ out, long long plane)
{
    extern __shared__ char sm[];
    __shared__ int s_item;
    const uint32_t smb = cvta_s(sm);

    const int tid  = threadIdx.x;
    const int w    = tid >> 5;
    const int lane = tid & 31;
    const int g4   = lane >> 2;
    const int j4   = lane & 3;
    const int r0   = w * 16 + g4;      // rows 0..127

    // ldmatrix lane base: lanes 0-7 plane0 k-low rows, 8-15 plane0 k-high,
    // 16-23 plane1 k-low, 24-31 plane1 k-high (layout verified in R8).
    const uint32_t laneLM = (uint32_t)((lane & 7) * ROWB)
                          + ((lane & 8) ? 16u : 0u)
                          + ((lane & 16) ? (uint32_t)PL_STR : 0u);

    // cp.async chunk map: 2048 chunks of 16B per tile (K 2 planes + Vt 2 planes)
    const int ci   = tid;                 // + it*256

    for (;;) {
        if (tid == 0) s_item = (int)atomicAdd(&g_ticket, 1u);
        __syncthreads();
        const int item = s_item;
        if (item >= NITEMS) break;

        const int bh  = item >> 4;
        const int s0t = (item & 15) * QT;
        const long long bbH = (long long)bh * S_LEN * DH;   // half-element base (K/Q)

        auto copy_tile = [&](int t, int buf) {
            #pragma unroll
            for (int it = 0; it < 8; ++it) {
                const int i = ci + it * THREADS;
                const int tensor = i >> 10;          // 0:K 1:Vt
                const int pl  = (i >> 9) & 1;
                const int row = (i >> 3) & 63;
                const int c16 = i & 7;
                const __half* src;
                uint32_t dst;
                if (tensor == 0) {
                    src = (pl ? gKi : gKr) + bbH + (long long)(t * NT + row) * DH + c16 * 8;
                    dst = smb + (uint32_t)KP(buf, pl) + (uint32_t)(row * ROWB + c16 * 16);
                } else {
                    src = (pl ? gVti : gVtr) + bbH + (long long)row * S_LEN + t * NT + c16 * 8;
                    dst = smb + (uint32_t)VP(buf, pl) + (uint32_t)(row * ROWB + c16 * 16);
                }
                cpa16(dst, src);
            }
            CP_COMMIT();
        };

        // ---- Q fragments -> registers (fp16 gmem, already scaled) ----
        uint32_t qfr[4][4], qfi[4][4];
        {
            const long long b0 = bbH + (long long)(s0t + r0) * DH;
            const long long b8 = bbH + (long long)(s0t + r0 + 8) * DH;
            #pragma unroll
            for (int ks = 0; ks < 4; ++ks) {
                const int c = ks * 16 + 2 * j4;
                qfr[ks][0] = *(const uint32_t*)(gQr + b0 + c);
                qfr[ks][1] = *(const uint32_t*)(gQr + b8 + c);
                qfr[ks][2] = *(const uint32_t*)(gQr + b0 + c + 8);
                qfr[ks][3] = *(const uint32_t*)(gQr + b8 + c + 8);
                qfi[ks][0] = *(const uint32_t*)(gQi + b0 + c);
                qfi[ks][1] = *(const uint32_t*)(gQi + b8 + c);
                qfi[ks][2] = *(const uint32_t*)(gQi + b0 + c + 8);
                qfi[ks][3] = *(const uint32_t*)(gQi + b8 + c + 8);
            }
        }

        copy_tile(0, 0);

        float ore[8][4], oim[8][4];
        #pragma unroll
        for (int nb = 0; nb < 8; ++nb)
            #pragma unroll
            for (int c = 0; c < 4; ++c) { ore[nb][c] = 0.f; oim[nb][c] = 0.f; }
        float l0 = 0.f, l1 = 0.f;

        for (int t = 0; t < NTILES; ++t) {
            const int cur = t & 1;
            CP_WAIT0();
            __syncthreads();      // tile t resident; everyone done reading buf cur^1
            if (t + 1 < NTILES) copy_tile(t + 1, cur ^ 1);

            // ---- GEMM1: S[16 x 64] complex ----
            float sre[8][4], sim[8][4];
            #pragma unroll
            for (int nb = 0; nb < 8; ++nb)
                #pragma unroll
                for (int c = 0; c < 4; ++c) { sre[nb][c] = 0.f; sim[nb][c] = 0.f; }

            const uint32_t kbase = smb + (uint32_t)KP(cur, 0) + laneLM;
            #pragma unroll
            for (int ks = 0; ks < 4; ++ks) {
                uint32_t nqb[4];
                #pragma unroll
                for (int k = 0; k < 4; ++k) nqb[k] = qfi[ks][k] ^ 0x80008000u;
                #pragma unroll
                for (int nb = 0; nb < 8; ++nb) {
                    uint4 f = ldsm4(kbase + nb * (8 * ROWB) + ks * 32);
                    mma16(sre[nb], qfr[ks], f.x, f.y);
                    mma16(sre[nb], nqb,     f.z, f.w);
                    mma16(sim[nb], qfr[ks], f.z, f.w);
                    mma16(sim[nb], qfi[ks], f.x, f.y);
                }
            }

            // ---- cv-softmax epilogue (register-local) ----
            #pragma unroll
            for (int nb = 0; nb < 8; ++nb) {
                #pragma unroll
                for (int c = 0; c < 4; ++c) {
                    float re = sre[nb][c], im = sim[nb][c];
                    float m2  = fmaxf(fmaf(re, re, im * im), 1e-24f);
                    float inv = rsqrtf(m2);
                    float mag = m2 * inv;
                    float e   = __expf(mag);
                    if (c < 2) l0 += e; else l1 += e;
                    float p = e * inv;
                    sre[nb][c] = re * p;
                    sim[nb][c] = im * p;
                }
            }

            // ---- GEMM2: O += P @ V (A-frag = packed C-frag pairs) ----
            const uint32_t vbase = smb + (uint32_t)VP(cur, 0) + laneLM;
            #pragma unroll
            for (int ks = 0; ks < 4; ++ks) {
                uint32_t pa[4], pb[4], npb[4];
                pa[0] = pkh(sre[2*ks][0],   sre[2*ks][1]);
                pa[1] = pkh(sre[2*ks][2],   sre[2*ks][3]);
                pa[2] = pkh(sre[2*ks+1][0], sre[2*ks+1][1]);
                pa[3] = pkh(sre[2*ks+1][2], sre[2*ks+1][3]);
                pb[0] = pkh(sim[2*ks][0],   sim[2*ks][1]);
                pb[1] = pkh(sim[2*ks][2],   sim[2*ks][3]);
                pb[2] = pkh(sim[2*ks+1][0], sim[2*ks+1][1]);
                pb[3] = pkh(sim[2*ks+1][2], sim[2*ks+1][3]);
                #pragma unroll
                for (int k = 0; k < 4; ++k) npb[k] = pb[k] ^ 0x80008000u;

                #pragma unroll
                for (int nb = 0; nb < 8; ++nb) {
                    uint4 f = ldsm4(vbase + nb * (8 * ROWB) + ks * 32);
                    mma16(ore[nb], pa,  f.x, f.y);
                    mma16(ore[nb], npb, f.z, f.w);
                    mma16(oim[nb], pa,  f.z, f.w);
                    mma16(oim[nb], pb,  f.x, f.y);
                }
            }
        }

        __syncthreads();   // all reads of smem tiles done; reuse as output stage

        l0 += __shfl_xor_sync(~0u, l0, 1); l0 += __shfl_xor_sync(~0u, l0, 2);
        l1 += __shfl_xor_sync(~0u, l1, 1); l1 += __shfl_xor_sync(~0u, l1, 2);
        const float il0 = 1.0f / l0, il1 = 1.0f / l1;

        float* stg = (float*)sm;            // [128][132]: 0..63 re, 64..127 im
        #pragma unroll
        for (int nb = 0; nb < 8; ++nb) {
            const int d0 = nb * 8 + 2 * j4;
            stg[ r0      * 132 + d0    ]      = ore[nb][0] * il0;
            stg[ r0      * 132 + d0 + 1]      = ore[nb][1] * il0;
            stg[(r0 + 8) * 132 + d0    ]      = ore[nb][2] * il1;
            stg[(r0 + 8) * 132 + d0 + 1]      = ore[nb][3] * il1;
            stg[ r0      * 132 + 64 + d0]     = oim[nb][0] * il0;
            stg[ r0      * 132 + 64 + d0 + 1] = oim[nb][1] * il0;
            stg[(r0 + 8) * 132 + 64 + d0]     = oim[nb][2] * il1;
            stg[(r0 + 8) * 132 + 64 + d0 + 1] = oim[nb][3] * il1;
        }
        __syncthreads();

        for (int i = tid; i < QT * 32; i += THREADS) {
            const int row = i >> 5, c = i & 31;
            float4 v = *(const float4*)(stg + row * 132 + c * 4);
            if (c < 16)
                *(float4*)(out + bbH + (long long)(s0t + row) * DH + c * 4) = v;
            else
                *(float4*)(out + plane + bbH + (long long)(s0t + row) * DH + (c - 16) * 4) = v;
        }
        __syncthreads();   // stage consumed before next item's tile copies land
    }
}

extern "C" void kernel_launch(void* const* d_in, const int* in_sizes, int n_in,
                              void* d_out, int out_size) {
    const float* qr = (const float*)d_in[0];
    const float* qi = (const float*)d_in[1];
    const float* kr = (const float*)d_in[2];
    const float* ki = (const float*)d_in[3];
    const float* vr = (const float*)d_in[4];
    const float* vi = (const float*)d_in[5];

    const long long plane = (long long)in_sizes[0];   // B*H*S*D

    static int configured = 0;
    if (!configured) {
        cudaFuncSetAttribute(cv_attn_h4_kernel,
                             cudaFuncAttributeMaxDynamicSharedMemorySize, SMEM_BYTES);
        configured = 1;
    }

    reset_ticket_kernel<<<1, 1>>>();
    {
        dim3 g(1024, 4);
        conv_kernel<<<g, 256>>>(qr, qi, kr, ki);
    }
    {
        dim3 g(S_LEN / 32, DH / 32, BH);
        prep_vt_kernel<<<g, dim3(32, 8)>>>(vr, vi);
    }
    cv_attn_h4_kernel<<<GRID, THREADS, SMEM_BYTES>>>((float*)d_out, plane);
}

// round 11
// speedup vs baseline: 2.6901x; 1.1007x over previous
#include <cuda_runtime.h>
#include <cuda_fp16.h>
#include <cstdint>

// Complex attention, fp16 m16n8k16 mma.sync.
// R10 skeleton (prep->fp16 gmem, cp.async dbuf, ldmatrix, reg-local softmax)
// with 128-thread CTAs (QT=64) x 2 CTAs/SM to decorrelate barrier/epilogue
// stalls across the SMSP's two warps.

#define S_LEN   2048
#define DH      64
#define BH      32
#define QT      64
#define NT      64
#define NTILES  (S_LEN / NT)
#define THREADS 128
#define NITEMS  1024            // 32 q-tiles x 32 heads
#define GRID    304             // 2 CTAs per SM
#define ROWB    176             // smem row stride (88 halves): conflict-free ldsm
#define PL_STR  (NT * ROWB)     // 11264

#define KP(buf, pl) (((buf) * 2 + (pl)) * PL_STR)
#define V_B     (4 * PL_STR)
#define VP(buf, pl) (V_B + ((buf) * 2 + (pl)) * PL_STR)
#define SMEM_BYTES (8 * PL_STR) // 90112

#define ELEMS (BH * S_LEN * DH)

__device__ __align__(16) __half gQr[ELEMS];
__device__ __align__(16) __half gQi[ELEMS];
__device__ __align__(16) __half gKr[ELEMS];
__device__ __align__(16) __half gKi[ELEMS];
__device__ __align__(16) __half gVtr[ELEMS];   // [bh][d][s]
__device__ __align__(16) __half gVti[ELEMS];

__device__ unsigned int g_ticket;
__global__ void reset_ticket_kernel() { g_ticket = 0u; }

// ---- prep: elementwise fp32 -> fp16 (Q scaled by 1/8) ----
__global__ void conv_kernel(const float* __restrict__ q_r, const float* __restrict__ q_i,
                            const float* __restrict__ k_r, const float* __restrict__ k_i)
{
    const int ts = blockIdx.y;
    const float* src = (ts == 0) ? q_r : (ts == 1) ? q_i : (ts == 2) ? k_r : k_i;
    __half* dst = (ts == 0) ? gQr : (ts == 1) ? gQi : (ts == 2) ? gKr : gKi;
    const float sc = (ts < 2) ? 0.125f : 1.0f;
    const int n4 = ELEMS / 4;
    for (int i = blockIdx.x * blockDim.x + threadIdx.x; i < n4; i += gridDim.x * blockDim.x) {
        float4 v = ((const float4*)src)[i];
        __half2* d2 = (__half2*)(dst + (size_t)i * 4);
        d2[0] = __floats2half2_rn(v.x * sc, v.y * sc);
        d2[1] = __floats2half2_rn(v.z * sc, v.w * sc);
    }
}

// ---- prep: V [s][d] fp32 -> Vt [d][s] fp16 (tiled transpose) ----
__global__ void prep_vt_kernel(const float* __restrict__ v_r, const float* __restrict__ v_i)
{
    __shared__ float tr[32][33], ti[32][33];
    const int s0 = blockIdx.x * 32, d0 = blockIdx.y * 32, bh = blockIdx.z;
    const int tx = threadIdx.x, ty = threadIdx.y;
    const long long ib = (long long)bh * S_LEN * DH;
    #pragma unroll
    for (int k = 0; k < 4; ++k) {
        int r = ty + k * 8;
        tr[r][tx] = v_r[ib + (long long)(s0 + r) * DH + d0 + tx];
        ti[r][tx] = v_i[ib + (long long)(s0 + r) * DH + d0 + tx];
    }
    __syncthreads();
    const long long ob = (long long)bh * DH * S_LEN;
    #pragma unroll
    for (int k = 0; k < 4; ++k) {
        int r = ty + k * 8;
        gVtr[ob + (long long)(d0 + r) * S_LEN + s0 + tx] = __float2half_rn(tr[tx][r]);
        gVti[ob + (long long)(d0 + r) * S_LEN + s0 + tx] = __float2half_rn(ti[tx][r]);
    }
}

// ---- helpers ----
__device__ __forceinline__ uint32_t cvta_s(const void* p) {
    uint32_t a;
    asm("{ .reg .u64 t; cvta.to.shared.u64 t, %1; cvt.u32.u64 %0, t; }" : "=r"(a) : "l"(p));
    return a;
}
__device__ __forceinline__ void cpa16(uint32_t dst, const void* src) {
    asm volatile("cp.async.ca.shared.global [%0], [%1], 16;" :: "r"(dst), "l"(src));
}
#define CP_COMMIT() asm volatile("cp.async.commit_group;" ::: "memory")
#define CP_WAIT0()  asm volatile("cp.async.wait_group 0;" ::: "memory")

__device__ __forceinline__ uint32_t pkh(float lo, float hi) {
    uint32_t d; asm("cvt.rn.f16x2.f32 %0, %1, %2;" : "=r"(d) : "f"(hi), "f"(lo)); return d;
}
__device__ __forceinline__ uint4 ldsm4(uint32_t a) {
    uint4 r;
    asm volatile("ldmatrix.sync.aligned.m8n8.x4.shared.b16 {%0,%1,%2,%3}, [%4];"
        : "=r"(r.x), "=r"(r.y), "=r"(r.z), "=r"(r.w) : "r"(a));
    return r;
}
__device__ __forceinline__ void mma16(float* d, const uint32_t* a, uint32_t b0, uint32_t b1) {
    asm volatile(
        "mma.sync.aligned.m16n8k16.row.col.f32.f16.f16.f32 "
        "{%0,%1,%2,%3}, {%4,%5,%6,%7}, {%8,%9}, {%0,%1,%2,%3};"
        : "+f"(d[0]), "+f"(d[1]), "+f"(d[2]), "+f"(d[3])
        : "r"(a[0]), "r"(a[1]), "r"(a[2]), "r"(a[3]), "r"(b0), "r"(b1));
}

__global__ __launch_bounds__(THREADS, 2)
void cv_attn_h5_kernel(float* __restrict__ out, long long plane)
{
    extern __shared__ char sm[];
    __shared__ int s_item;
    const uint32_t smb = cvta_s(sm);

    const int tid  = threadIdx.x;
    const int w    = tid >> 5;         // 0..3
    const int lane = tid & 31;
    const int g4   = lane >> 2;
    const int j4   = lane & 3;
    const int r0   = w * 16 + g4;      // rows 0..63

    const uint32_t laneLM = (uint32_t)((lane & 7) * ROWB)
                          + ((lane & 8) ? 16u : 0u)
                          + ((lane & 16) ? (uint32_t)PL_STR : 0u);

    for (;;) {
        if (tid == 0) s_item = (int)atomicAdd(&g_ticket, 1u);
        __syncthreads();
        const int item = s_item;
        if (item >= NITEMS) break;

        const int bh  = item >> 5;
        const int s0t = (item & 31) * QT;
        const long long bbH = (long long)bh * S_LEN * DH;

        auto copy_tile = [&](int t, int buf) {
            #pragma unroll
            for (int it = 0; it < 16; ++it) {
                const int i = tid + it * THREADS;    // 2048 x 16B chunks
                const int tensor = i >> 10;          // 0:K 1:Vt
                const int pl  = (i >> 9) & 1;
                const int row = (i >> 3) & 63;
                const int c16 = i & 7;
                const __half* src;
                uint32_t dst;
                if (tensor == 0) {
                    src = (pl ? gKi : gKr) + bbH + (long long)(t * NT + row) * DH + c16 * 8;
                    dst = smb + (uint32_t)KP(buf, pl) + (uint32_t)(row * ROWB + c16 * 16);
                } else {
                    src = (pl ? gVti : gVtr) + bbH + (long long)row * S_LEN + t * NT + c16 * 8;
                    dst = smb + (uint32_t)VP(buf, pl) + (uint32_t)(row * ROWB + c16 * 16);
                }
                cpa16(dst, src);
            }
            CP_COMMIT();
        };

        // ---- Q fragments -> registers (fp16 gmem, already scaled) ----
        uint32_t qfr[4][4], qfi[4][4];
        {
            const long long b0 = bbH + (long long)(s0t + r0) * DH;
            const long long b8 = bbH + (long long)(s0t + r0 + 8) * DH;
            #pragma unroll
            for (int ks = 0; ks < 4; ++ks) {
                const int c = ks * 16 + 2 * j4;
                qfr[ks][0] = *(const uint32_t*)(gQr + b0 + c);
                qfr[ks][1] = *(const uint32_t*)(gQr + b8 + c);
                qfr[ks][2] = *(const uint32_t*)(gQr + b0 + c + 8);
                qfr[ks][3] = *(const uint32_t*)(gQr + b8 + c + 8);
                qfi[ks][0] = *(const uint32_t*)(gQi + b0 + c);
                qfi[ks][1] = *(const uint32_t*)(gQi + b8 + c);
                qfi[ks][2] = *(const uint32_t*)(gQi + b0 + c + 8);
                qfi[ks][3] = *(const uint32_t*)(gQi + b8 + c + 8);
            }
        }

        copy_tile(0, 0);

        float ore[8][4], oim[8][4];
        #pragma unroll
        for (int nb = 0; nb < 8; ++nb)
            #pragma unroll
            for (int c = 0; c < 4; ++c) { ore[nb][c] = 0.f; oim[nb][c] = 0.f; }
        float l0 = 0.f, l1 = 0.f;

        for (int t = 0; t < NTILES; ++t) {
            const int cur = t & 1;
            CP_WAIT0();
            __syncthreads();
            if (t + 1 < NTILES) copy_tile(t + 1, cur ^ 1);

            // ---- GEMM1: S[16 x 64] complex ----
            float sre[8][4], sim[8][4];
            #pragma unroll
            for (int nb = 0; nb < 8; ++nb)
                #pragma unroll
                for (int c = 0; c < 4; ++c) { sre[nb][c] = 0.f; sim[nb][c] = 0.f; }

            const uint32_t kbase = smb + (uint32_t)KP(cur, 0) + laneLM;
            #pragma unroll
            for (int ks = 0; ks < 4; ++ks) {
                uint32_t nqb[4];
                #pragma unroll
                for (int k = 0; k < 4; ++k) nqb[k] = qfi[ks][k] ^ 0x80008000u;
                #pragma unroll
                for (int nb = 0; nb < 8; ++nb) {
                    uint4 f = ldsm4(kbase + nb * (8 * ROWB) + ks * 32);
                    mma16(sre[nb], qfr[ks], f.x, f.y);
                    mma16(sre[nb], nqb,     f.z, f.w);
                    mma16(sim[nb], qfr[ks], f.z, f.w);
                    mma16(sim[nb], qfi[ks], f.x, f.y);
                }
            }

            // ---- cv-softmax epilogue (register-local) ----
            #pragma unroll
            for (int nb = 0; nb < 8; ++nb) {
                #pragma unroll
                for (int c = 0; c < 4; ++c) {
                    float re = sre[nb][c], im = sim[nb][c];
                    float m2  = fmaxf(fmaf(re, re, im * im), 1e-24f);
                    float inv = rsqrtf(m2);
                    float mag = m2 * inv;
                    float e   = __expf(mag);
                    if (c < 2) l0 += e; else l1 += e;
                    float p = e * inv;
                    sre[nb][c] = re * p;
                    sim[nb][c] = im * p;
                }
            }

            // ---- GEMM2: O += P @ V ----
            const uint32_t vbase = smb + (uint32_t)VP(cur, 0) + laneLM;
            #pragma unroll
            for (int ks = 0; ks < 4; ++ks) {
                uint32_t pa[4], pb[4], npb[4];
                pa[0] = pkh(sre[2*ks][0],   sre[2*ks][1]);
                pa[1] = pkh(sre[2*ks][2],   sre[2*ks][3]);
                pa[2] = pkh(sre[2*ks+1][0], sre[2*ks+1][1]);
                pa[3] = pkh(sre[2*ks+1][2], sre[2*ks+1][3]);
                pb[0] = pkh(sim[2*ks][0],   sim[2*ks][1]);
                pb[1] = pkh(sim[2*ks][2],   sim[2*ks][3]);
                pb[2] = pkh(sim[2*ks+1][0], sim[2*ks+1][1]);
                pb[3] = pkh(sim[2*ks+1][2], sim[2*ks+1][3]);
                #pragma unroll
                for (int k = 0; k < 4; ++k) npb[k] = pb[k] ^ 0x80008000u;

                #pragma unroll
                for (int nb = 0; nb < 8; ++nb) {
                    uint4 f = ldsm4(vbase + nb * (8 * ROWB) + ks * 32);
                    mma16(ore[nb], pa,  f.x, f.y);
                    mma16(ore[nb], npb, f.z, f.w);
                    mma16(oim[nb], pa,  f.z, f.w);
                    mma16(oim[nb], pb,  f.x, f.y);
                }
            }
        }

        __syncthreads();   // all smem tile reads done; reuse as output stage

        l0 += __shfl_xor_sync(~0u, l0, 1); l0 += __shfl_xor_sync(~0u, l0, 2);
        l1 += __shfl_xor_sync(~0u, l1, 1); l1 += __shfl_xor_sync(~0u, l1, 2);
        const float il0 = 1.0f / l0, il1 = 1.0f / l1;

        float* stg = (float*)sm;            // [64][132]: 0..63 re, 64..127 im
        #pragma unroll
        for (int nb = 0; nb < 8; ++nb) {
            const int d0 = nb * 8 + 2 * j4;
            stg[ r0      * 132 + d0    ]      = ore[nb][0] * il0;
            stg[ r0      * 132 + d0 + 1]      = ore[nb][1] * il0;
            stg[(r0 + 8) * 132 + d0    ]      = ore[nb][2] * il1;
            stg[(r0 + 8) * 132 + d0 + 1]      = ore[nb][3] * il1;
            stg[ r0      * 132 + 64 + d0]     = oim[nb][0] * il0;
            stg[ r0      * 132 + 64 + d0 + 1] = oim[nb][1] * il0;
            stg[(r0 + 8) * 132 + 64 + d0]     = oim[nb][2] * il1;
            stg[(r0 + 8) * 132 + 64 + d0 + 1] = oim[nb][3] * il1;
        }
        __syncthreads();

        for (int i = tid; i < QT * 32; i += THREADS) {
            const int row = i >> 5, c = i & 31;
            float4 v = *(const float4*)(stg + row * 132 + c * 4);
            if (c < 16)
                *(float4*)(out + bbH + (long long)(s0t + row) * DH + c * 4) = v;
            else
                *(float4*)(out + plane + bbH + (long long)(s0t + row) * DH + (c - 16) * 4) = v;
        }
        __syncthreads();   // stage consumed before next item's tile copies land
    }
}

extern "C" void kernel_launch(void* const* d_in, const int* in_sizes, int n_in,
                              void* d_out, int out_size) {
    const float* qr = (const float*)d_in[0];
    const float* qi = (const float*)d_in[1];
    const float* kr = (const float*)d_in[2];
    const float* ki = (const float*)d_in[3];
    const float* vr = (const float*)d_in[4];
    const float* vi = (const float*)d_in[5];

    const long long plane = (long long)in_sizes[0];   // B*H*S*D

    static int configured = 0;
    if (!configured) {
        cudaFuncSetAttribute(cv_attn_h5_kernel,
                             cudaFuncAttributeMaxDynamicSharedMemorySize, SMEM_BYTES);
        configured = 1;
    }

    reset_ticket_kernel<<<1, 1>>>();
    {
        dim3 g(1024, 4);
        conv_kernel<<<g, 256>>>(qr, qi, kr, ki);
    }
    {
        dim3 g(S_LEN / 32, DH / 32, BH);
        prep_vt_kernel<<<g, dim3(32, 8)>>>(vr, vi);
    }
    cv_attn_h5_kernel<<<GRID, THREADS, SMEM_BYTES>>>((float*)d_out, plane);
}